// round 2
// baseline (speedup 1.0000x reference)
#include <cuda_runtime.h>
#include <float.h>

#define NCH      36
#define NANCH    8400
#define NCLS     32
#define MAXDET   100
#define BATCH    64
#define NTHREADS 1024
#define KPT      9      // ceil(8400/1024)
#define CONF_T   0.25f
#define IOU_T    0.45f

// dynamic smem: float4 box[8400] + float area[8400] + float cls[8400]
#define SMEM_BYTES ((4 + 1 + 1) * NANCH * 4)

__global__ __launch_bounds__(NTHREADS, 1)
void yolo_nms_kernel(const float* __restrict__ in, float* __restrict__ out) {
    extern __shared__ float smem[];
    float4* sbox = (float4*)smem;            // [8400] (y1,x1,y2,x2)
    float*  sarea = smem + 4 * NANCH;        // [8400]
    float*  scls  = smem + 5 * NANCH;        // [8400]
    __shared__ float rs[32];
    __shared__ int   ri[32];
    __shared__ float bc_s;
    __shared__ int   bc_i;

    const int img = blockIdx.x;
    const int tid = threadIdx.x;
    const float* base = in + (size_t)img * NCH * NANCH;

    // Output slices (tuple order: boxes, classes, scores, num_det)
    float* ob  = out + (size_t)img * MAXDET * 4;
    float* oc  = out + (size_t)BATCH * MAXDET * 4 + (size_t)img * MAXDET;
    float* osc = out + (size_t)BATCH * MAXDET * 4 + (size_t)BATCH * MAXDET + (size_t)img * MAXDET;
    float* ond = out + (size_t)BATCH * MAXDET * 4 + (size_t)BATCH * MAXDET * 2;

    // Pre-zero this image's output region (d_out is poisoned to 0xAA).
    for (int i = tid; i < MAXDET * 4; i += NTHREADS) ob[i] = 0.0f;
    if (tid < MAXDET) { oc[tid] = 0.0f; osc[tid] = 0.0f; }

    // ---- Phase 1: preprocess 8400 anchors into SMEM/regs ----
    float score[KPT];
    #pragma unroll
    for (int k = 0; k < KPT; k++) {
        int idx = tid + k * NTHREADS;
        float s = -FLT_MAX;
        if (idx < NANCH) {
            float xc = base[0 * NANCH + idx];
            float yc = base[1 * NANCH + idx];
            float w  = base[2 * NANCH + idx];
            float h  = base[3 * NANCH + idx];
            float best = -FLT_MAX;
            int cls = 0;
            #pragma unroll
            for (int c = 0; c < NCLS; c++) {
                float v = base[(4 + c) * NANCH + idx];
                if (v > best) { best = v; cls = c; }   // strict > == first-max (jnp.argmax)
            }
            // clip(v,0,1) = min(max(v,0),1); 0.5f*h exact -> FMA-safe
            float y1 = fminf(fmaxf(yc - 0.5f * h, 0.0f), 1.0f);
            float x1 = fminf(fmaxf(xc - 0.5f * w, 0.0f), 1.0f);
            float y2 = fminf(fmaxf(yc + 0.5f * h, 0.0f), 1.0f);
            float x2 = fminf(fmaxf(xc + 0.5f * w, 0.0f), 1.0f);
            sbox[idx]  = make_float4(y1, x1, y2, x2);
            sarea[idx] = (y2 - y1) * (x2 - x1);
            scls[idx]  = (float)cls;
            s = (best >= CONF_T) ? best : -1.0f;
        }
        score[k] = s;
    }
    __syncthreads();

    // ---- Phase 2: sequential NMS, 100 steps ----
    int ndet = 0;
    for (int d = 0; d < MAXDET; d++) {
        // local argmax with first-index tie-break
        float ls = -FLT_MAX;
        int   li = 0x7FFFFFFF;
        #pragma unroll
        for (int k = 0; k < KPT; k++) {
            int idx = tid + k * NTHREADS;
            float s = score[k];
            if (s > ls || (s == ls && idx < li)) { ls = s; li = idx; }
        }
        // warp butterfly reduce (lexicographic: max score, then min idx)
        #pragma unroll
        for (int off = 16; off > 0; off >>= 1) {
            float os2 = __shfl_xor_sync(0xFFFFFFFFu, ls, off);
            int   oi  = __shfl_xor_sync(0xFFFFFFFFu, li, off);
            if (os2 > ls || (os2 == ls && oi < li)) { ls = os2; li = oi; }
        }
        if ((tid & 31) == 0) { rs[tid >> 5] = ls; ri[tid >> 5] = li; }
        __syncthreads();
        if (tid < 32) {
            ls = rs[tid]; li = ri[tid];
            #pragma unroll
            for (int off = 16; off > 0; off >>= 1) {
                float os2 = __shfl_xor_sync(0xFFFFFFFFu, ls, off);
                int   oi  = __shfl_xor_sync(0xFFFFFFFFu, li, off);
                if (os2 > ls || (os2 == ls && oi < li)) { ls = os2; li = oi; }
            }
            if (tid == 0) { bc_s = ls; bc_i = li; }
        }
        __syncthreads();

        float sb = bc_s;
        int   ib = bc_i;
        if (!(sb > 0.0f)) break;   // uniform across block; remaining outputs stay zero
        ndet++;

        float4 bb = sbox[ib];      // broadcast LDS
        float barea = sarea[ib];

        if (tid == 0) {
            ob[d * 4 + 0] = bb.x; ob[d * 4 + 1] = bb.y;
            ob[d * 4 + 2] = bb.z; ob[d * 4 + 3] = bb.w;
            oc[d] = scls[ib];
            osc[d] = sb;
        }

        // suppress: iou > 0.45 -> -1; selected idx forced -1
        #pragma unroll
        for (int k = 0; k < KPT; k++) {
            int idx = tid + k * NTHREADS;
            if (score[k] > 0.0f) {        // dead/masked anchors need no work
                if (idx == ib) {
                    score[k] = -1.0f;
                } else {
                    float4 b  = sbox[idx];
                    float ab  = sarea[idx];
                    float yy1 = fmaxf(bb.x, b.x);
                    float xx1 = fmaxf(bb.y, b.y);
                    float yy2 = fminf(bb.z, b.z);
                    float xx2 = fminf(bb.w, b.w);
                    float inter = fmaxf(yy2 - yy1, 0.0f) * fmaxf(xx2 - xx1, 0.0f);
                    float uni = barea + ab - inter;   // area_a + area_b - inter (ref order)
                    bool sup = false;
                    if (uni > 0.0f) sup = (inter / uni) > IOU_T;  // IEEE div.rn, matches XLA
                    if (sup) score[k] = -1.0f;
                }
            }
        }
        __syncthreads();
    }

    if (tid == 0) ond[img] = (float)ndet;
}

extern "C" void kernel_launch(void* const* d_in, const int* in_sizes, int n_in,
                              void* d_out, int out_size) {
    static bool attr_done = false;
    if (!attr_done) {
        cudaFuncSetAttribute(yolo_nms_kernel,
                             cudaFuncAttributeMaxDynamicSharedMemorySize, SMEM_BYTES);
        attr_done = true;
    }
    const float* in = (const float*)d_in[0];
    float* out = (float*)d_out;
    yolo_nms_kernel<<<BATCH, NTHREADS, SMEM_BYTES>>>(in, out);
}

// round 3
// speedup vs baseline: 1.5400x; 1.5400x over previous
#include <cuda_runtime.h>
#include <float.h>

#define NCH      36
#define NANCH    8400
#define NCLS     32
#define MAXDET   100
#define BATCH    64
#define NTHREADS 1024
#define KPT      9      // ceil(8400/1024)
#define CONF_T   0.25f

// dynamic smem: float4 box[8400] + float area[8400] + float cls[8400]
#define SMEM_BYTES ((4 + 1 + 1) * NANCH * 4)

__global__ __launch_bounds__(NTHREADS, 1)
void yolo_nms_kernel(const float* __restrict__ in, float* __restrict__ out) {
    extern __shared__ float smem[];
    float4* sbox  = (float4*)smem;           // [8400] (y1,x1,y2,x2)
    float*  sarea = smem + 4 * NANCH;        // [8400]
    float*  scls  = smem + 5 * NANCH;        // [8400]
    __shared__ uint2 red[64];                // double-buffered 2 x 32 (score_bits, idx)

    const int img = blockIdx.x;
    const int tid = threadIdx.x;
    const int lane = tid & 31;
    const int wid  = tid >> 5;
    const float* base = in + (size_t)img * NCH * NANCH;

    // Output slices (tuple order: boxes, classes, scores, num_det)
    float* ob  = out + (size_t)img * MAXDET * 4;
    float* oc  = out + (size_t)BATCH * MAXDET * 4 + (size_t)img * MAXDET;
    float* osc = out + (size_t)BATCH * MAXDET * 4 + (size_t)BATCH * MAXDET + (size_t)img * MAXDET;
    float* ond = out + (size_t)BATCH * MAXDET * 4 + (size_t)BATCH * MAXDET * 2;

    // Pre-zero this image's output region (d_out is poisoned to 0xAA).
    for (int i = tid; i < MAXDET * 4; i += NTHREADS) ob[i] = 0.0f;
    if (tid < MAXDET) { oc[tid] = 0.0f; osc[tid] = 0.0f; }

    // ---- Phase 1: preprocess 8400 anchors into SMEM/regs ----
    float score[KPT];
    #pragma unroll
    for (int k = 0; k < KPT; k++) {
        int idx = tid + k * NTHREADS;
        float s = -FLT_MAX;
        if (idx < NANCH) {
            float xc = base[0 * NANCH + idx];
            float yc = base[1 * NANCH + idx];
            float w  = base[2 * NANCH + idx];
            float h  = base[3 * NANCH + idx];
            float best = -FLT_MAX;
            int cls = 0;
            #pragma unroll
            for (int c = 0; c < NCLS; c++) {
                float v = base[(4 + c) * NANCH + idx];
                if (v > best) { best = v; cls = c; }   // strict > == first-max (jnp.argmax)
            }
            float y1 = fminf(fmaxf(yc - 0.5f * h, 0.0f), 1.0f);
            float x1 = fminf(fmaxf(xc - 0.5f * w, 0.0f), 1.0f);
            float y2 = fminf(fmaxf(yc + 0.5f * h, 0.0f), 1.0f);
            float x2 = fminf(fmaxf(xc + 0.5f * w, 0.0f), 1.0f);
            sbox[idx]  = make_float4(y1, x1, y2, x2);
            sarea[idx] = (y2 - y1) * (x2 - x1);
            scls[idx]  = (float)cls;
            s = (best >= CONF_T) ? best : -1.0f;
        }
        score[k] = s;
    }
    __syncthreads();

    // ---- Phase 2: sequential NMS, 100 steps, ONE barrier per step ----
    // Local argmax for the first iteration (first-index tie-break).
    float ls = -FLT_MAX;
    int   li = 0x7FFFFFFF;
    #pragma unroll
    for (int k = 0; k < KPT; k++) {
        int idx = tid + k * NTHREADS;
        float s = score[k];
        if (s > ls || (s == ls && idx < li)) { ls = s; li = idx; }
    }

    int ndet = 0;
    for (int d = 0; d < MAXDET; d++) {
        // warp butterfly reduce (lexicographic: max score, then min idx)
        #pragma unroll
        for (int off = 16; off > 0; off >>= 1) {
            float os = __shfl_xor_sync(0xFFFFFFFFu, ls, off);
            int   oi = __shfl_xor_sync(0xFFFFFFFFu, li, off);
            if (os > ls || (os == ls && oi < li)) { ls = os; li = oi; }
        }
        if (lane == 0)
            red[(d & 1) * 32 + wid] = make_uint2(__float_as_uint(ls), (unsigned)li);
        __syncthreads();

        // stage 2: every warp redundantly reduces the 32 per-warp winners
        uint2 v = red[(d & 1) * 32 + lane];
        float sb = __uint_as_float(v.x);
        int   ib = (int)v.y;
        #pragma unroll
        for (int off = 16; off > 0; off >>= 1) {
            float os = __shfl_xor_sync(0xFFFFFFFFu, sb, off);
            int   oi = __shfl_xor_sync(0xFFFFFFFFu, ib, off);
            if (os > sb || (os == sb && oi < ib)) { sb = os; ib = oi; }
        }

        if (!(sb > 0.0f)) break;   // uniform across block
        ndet++;

        float4 bb = sbox[ib];      // broadcast LDS
        float  ba = sarea[ib];

        if (tid == 0) {
            ob[d * 4 + 0] = bb.x; ob[d * 4 + 1] = bb.y;
            ob[d * 4 + 2] = bb.z; ob[d * 4 + 3] = bb.w;
            oc[d]  = scls[ib];
            osc[d] = sb;
        }

        // Fused suppress + next local argmax.
        // iou > 0.45 decided via guarded multiplies; exact IEEE div only in the
        // (vanishingly rare) ambiguity band -> bitwise-identical to reference.
        ls = -FLT_MAX;
        li = 0x7FFFFFFF;
        #pragma unroll
        for (int k = 0; k < KPT; k++) {
            int idx = tid + k * NTHREADS;
            float s = score[k];
            if (s > 0.0f) {
                if (idx == ib) {
                    s = -1.0f;
                } else {
                    float4 b  = sbox[idx];
                    float  ab = sarea[idx];
                    float yy1 = fmaxf(bb.x, b.x);
                    float xx1 = fmaxf(bb.y, b.y);
                    float yy2 = fminf(bb.z, b.z);
                    float xx2 = fminf(bb.w, b.w);
                    float inter = fmaxf(yy2 - yy1, 0.0f) * fmaxf(xx2 - xx1, 0.0f);
                    float uni = ba + ab - inter;   // area_a + area_b - inter (ref order)
                    if (uni > 0.0f) {
                        float hib = 0.45000051f * uni;   // +1.1e-6 rel guard
                        float lob = 0.44999949f * uni;   // -1.1e-6 rel guard
                        if (inter > hib) {
                            s = -1.0f;
                        } else if (!(inter < lob)) {
                            // ambiguous band: exact IEEE div.rn, matches XLA
                            if ((inter / uni) > 0.45f) s = -1.0f;
                        }
                    }
                }
                score[k] = s;
            }
            if (s > ls || (s == ls && idx < li)) { ls = s; li = idx; }
        }
    }

    if (tid == 0) ond[img] = (float)ndet;
}

extern "C" void kernel_launch(void* const* d_in, const int* in_sizes, int n_in,
                              void* d_out, int out_size) {
    static bool attr_done = false;
    if (!attr_done) {
        cudaFuncSetAttribute(yolo_nms_kernel,
                             cudaFuncAttributeMaxDynamicSharedMemorySize, SMEM_BYTES);
        attr_done = true;
    }
    const float* in = (const float*)d_in[0];
    float* out = (float*)d_out;
    yolo_nms_kernel<<<BATCH, NTHREADS, SMEM_BYTES>>>(in, out);
}

// round 7
// speedup vs baseline: 1.8177x; 1.1803x over previous
#include <cuda_runtime.h>
#include <float.h>
#include <cstdint>

#define NCH       36
#define NANCH     8400
#define NCLS      32
#define MAXDET    100
#define BATCH     64
#define NTHREADS  1024
#define CLUSTER   2
#define HALF_ANCH 4200            // anchors per CTA
#define KPT       5               // ceil(4200/1024)
#define CONF_T    0.25f

// dynamic smem per CTA: float4 box[4200] + area[4200] + cls[4200]
#define SMEM_BYTES ((4 + 1 + 1) * HALF_ANCH * 4)

__device__ __forceinline__ uint32_t smem_u32(const void* p) {
    uint32_t a;
    asm("{ .reg .u64 t; cvta.to.shared.u64 t, %1; cvt.u32.u64 %0, t; }" : "=r"(a) : "l"(p));
    return a;
}
__device__ __forceinline__ uint32_t mapa_u32(uint32_t a, uint32_t rank) {
    uint32_t o;
    asm("mapa.shared::cluster.u32 %0, %1, %2;" : "=r"(o) : "r"(a), "r"(rank));
    return o;
}
__device__ __forceinline__ void st_cluster(uint32_t a, unsigned v) {
    asm volatile("st.shared::cluster.u32 [%0], %1;" :: "r"(a), "r"(v) : "memory");
}

__global__ __launch_bounds__(NTHREADS, 1) __cluster_dims__(CLUSTER, 1, 1)
void yolo_nms_kernel(const float* __restrict__ in, float* __restrict__ out) {
    extern __shared__ float smem[];
    float4* sbox  = (float4*)smem;             // [4200] (y1,x1,y2,x2)
    float*  sarea = smem + 4 * HALF_ANCH;      // [4200]
    float*  scls  = smem + 5 * HALF_ANCH;      // [4200]
    __shared__ uint2 red[64];                  // double-buffered 2 x 32
    __shared__ unsigned mail[2][8];            // peer-written candidate, parity-buffered
    __shared__ unsigned long long cbar;        // mbarrier

    const int tid  = threadIdx.x;
    const int lane = tid & 31;
    const int wid  = tid >> 5;
    unsigned rank;
    asm("mov.u32 %0, %%cluster_ctarank;" : "=r"(rank));
    const int img  = blockIdx.x >> 1;
    const int gbase = rank * HALF_ANCH;        // global anchor base for this CTA

    const float* base = in + (size_t)img * NCH * NANCH;

    // Output slices (tuple order: boxes, classes, scores, num_det)
    float* ob  = out + (size_t)img * MAXDET * 4;
    float* oc  = out + (size_t)BATCH * MAXDET * 4 + (size_t)img * MAXDET;
    float* osc = out + (size_t)BATCH * MAXDET * 4 + (size_t)BATCH * MAXDET + (size_t)img * MAXDET;
    float* ond = out + (size_t)BATCH * MAXDET * 4 + (size_t)BATCH * MAXDET * 2;

    // DSMEM addresses (computed once)
    const uint32_t bar_a   = smem_u32(&cbar);
    const uint32_t peer    = rank ^ 1u;
    const uint32_t r_bar   = mapa_u32(bar_a, peer);
    const uint32_t r_mail0 = mapa_u32(smem_u32(&mail[0][0]), peer);
    const uint32_t r_mail1 = mapa_u32(smem_u32(&mail[1][0]), peer);

    if (tid == 0) {
        asm volatile("mbarrier.init.shared.b64 [%0], %1;" :: "r"(bar_a), "r"(1u) : "memory");
    }

    // rank 0 pre-zeros this image's outputs (d_out poisoned to 0xAA)
    if (rank == 0) {
        for (int i = tid; i < MAXDET * 4; i += NTHREADS) ob[i] = 0.0f;
        if (tid < MAXDET) { oc[tid] = 0.0f; osc[tid] = 0.0f; }
    }

    // ---- Phase 1: preprocess this CTA's 4200 anchors ----
    float score[KPT];
    #pragma unroll
    for (int k = 0; k < KPT; k++) {
        int l = tid + k * NTHREADS;
        float s = -FLT_MAX;
        if (l < HALF_ANCH) {
            int ga = gbase + l;
            float xc = base[0 * NANCH + ga];
            float yc = base[1 * NANCH + ga];
            float w  = base[2 * NANCH + ga];
            float h  = base[3 * NANCH + ga];
            float best = -FLT_MAX;
            int cls = 0;
            #pragma unroll
            for (int c = 0; c < NCLS; c++) {
                float v = base[(4 + c) * NANCH + ga];
                if (v > best) { best = v; cls = c; }   // strict > == first-max
            }
            float y1 = fminf(fmaxf(yc - 0.5f * h, 0.0f), 1.0f);
            float x1 = fminf(fmaxf(xc - 0.5f * w, 0.0f), 1.0f);
            float y2 = fminf(fmaxf(yc + 0.5f * h, 0.0f), 1.0f);
            float x2 = fminf(fmaxf(xc + 0.5f * w, 0.0f), 1.0f);
            sbox[l]  = make_float4(y1, x1, y2, x2);
            sarea[l] = (y2 - y1) * (x2 - x1);
            scls[l]  = (float)cls;
            s = (best >= CONF_T) ? best : -1.0f;
        }
        score[k] = s;
    }
    __syncthreads();
    // mbarrier init visible cluster-wide before any remote arrive
    asm volatile("barrier.cluster.arrive.aligned;" ::: "memory");
    asm volatile("barrier.cluster.wait.aligned;"   ::: "memory");

    // first local argmax (global ids; first-index tie-break)
    float ls = -FLT_MAX;
    int   li = 0x7FFFFFFF;
    #pragma unroll
    for (int k = 0; k < KPT; k++) {
        int gi = gbase + tid + k * NTHREADS;
        float s = score[k];
        if (s > ls || (s == ls && gi < li)) { ls = s; li = gi; }
    }

    int ndet = 0;
    for (int d = 0; d < MAXDET; d++) {
        // warp butterfly (max score, then min global idx)
        #pragma unroll
        for (int off = 16; off > 0; off >>= 1) {
            float os = __shfl_xor_sync(0xFFFFFFFFu, ls, off);
            int   oi = __shfl_xor_sync(0xFFFFFFFFu, li, off);
            if (os > ls || (os == ls && oi < li)) { ls = os; li = oi; }
        }
        if (lane == 0)
            red[(d & 1) * 32 + wid] = make_uint2(__float_as_uint(ls), (unsigned)li);
        __syncthreads();

        // stage 2: every warp reduces the 32 per-warp winners -> CTA candidate
        uint2 v = red[(d & 1) * 32 + lane];
        float sb = __uint_as_float(v.x);
        int   ib = (int)v.y;
        #pragma unroll
        for (int off = 16; off > 0; off >>= 1) {
            float os = __shfl_xor_sync(0xFFFFFFFFu, sb, off);
            int   oi = __shfl_xor_sync(0xFFFFFFFFu, ib, off);
            if (os > sb || (os == sb && oi < ib)) { sb = os; ib = oi; }
        }

        // local winner attributes (always owned by this CTA)
        int lloc = ib - gbase;
        float4 wb = sbox[lloc];
        float  wa = sarea[lloc];
        float  wc = scls[lloc];

        // push candidate record to peer's mailbox (parity buffer), then arrive
        if (tid == 0) {
            uint32_t rm = (d & 1) ? r_mail1 : r_mail0;
            st_cluster(rm + 0,  __float_as_uint(sb));
            st_cluster(rm + 4,  (unsigned)ib);
            st_cluster(rm + 8,  __float_as_uint(wb.x));
            st_cluster(rm + 12, __float_as_uint(wb.y));
            st_cluster(rm + 16, __float_as_uint(wb.z));
            st_cluster(rm + 20, __float_as_uint(wb.w));
            st_cluster(rm + 24, __float_as_uint(wa));
            st_cluster(rm + 28, __float_as_uint(wc));
            asm volatile("mbarrier.arrive.shared::cluster.b64 _, [%0];"
                         :: "r"(r_bar) : "memory");
        }

        // wait for peer's candidate (phase parity = d&1)
        {
            unsigned done;
            asm volatile(
                "{\n\t.reg .pred p;\n\t"
                "mbarrier.try_wait.parity.relaxed.cta.shared::cta.b64 p, [%1], %2, 0x989680;\n\t"
                "selp.b32 %0, 1, 0, p;\n\t}"
                : "=r"(done) : "r"(bar_a), "r"((unsigned)(d & 1)) : "memory");
            if (!done) {
                asm volatile(
                    "{\n\t.reg .pred P1;\n\t"
                    "WL_%=:\n\t"
                    "mbarrier.try_wait.parity.relaxed.cta.shared::cta.b64 P1, [%0], %1, 0x989680;\n\t"
                    "@P1 bra.uni WD_%=;\n\t"
                    "bra.uni WL_%=;\n\t"
                    "WD_%=:\n\t}"
                    :: "r"(bar_a), "r"((unsigned)(d & 1)) : "memory");
            }
            asm volatile("fence.acq_rel.cluster;" ::: "memory");
        }

        // merge with remote candidate
        const unsigned* m = mail[d & 1];
        float rsb = __uint_as_float(m[0]);
        int   rib = (int)m[1];
        bool rwin = (rsb > sb) || (rsb == sb && rib < ib);
        float gs = rwin ? rsb : sb;
        int   gi = rwin ? rib : ib;

        if (!(gs > 0.0f)) break;   // uniform across cluster
        ndet++;

        float4 bb = rwin ? make_float4(__uint_as_float(m[2]), __uint_as_float(m[3]),
                                       __uint_as_float(m[4]), __uint_as_float(m[5]))
                         : wb;
        float  ba = rwin ? __uint_as_float(m[6]) : wa;

        if (rank == 0 && tid == 0) {
            ob[d * 4 + 0] = bb.x; ob[d * 4 + 1] = bb.y;
            ob[d * 4 + 2] = bb.z; ob[d * 4 + 3] = bb.w;
            oc[d]  = rwin ? __uint_as_float(m[7]) : wc;
            osc[d] = gs;
        }

        // fused suppress + next local argmax (guarded-mul IoU, exact-div fallback)
        ls = -FLT_MAX;
        li = 0x7FFFFFFF;
        #pragma unroll
        for (int k = 0; k < KPT; k++) {
            int l   = tid + k * NTHREADS;
            int gid = gbase + l;
            float s = score[k];
            if (s > 0.0f) {
                if (gid == gi) {
                    s = -1.0f;
                } else {
                    float4 b  = sbox[l];
                    float  ab = sarea[l];
                    float yy1 = fmaxf(bb.x, b.x);
                    float xx1 = fmaxf(bb.y, b.y);
                    float yy2 = fminf(bb.z, b.z);
                    float xx2 = fminf(bb.w, b.w);
                    float inter = fmaxf(yy2 - yy1, 0.0f) * fmaxf(xx2 - xx1, 0.0f);
                    float uni = ba + ab - inter;   // area_a + area_b - inter (ref order)
                    if (uni > 0.0f) {
                        float hib = 0.45000051f * uni;   // +1.1e-6 rel guard
                        float lob = 0.44999949f * uni;   // -1.1e-6 rel guard
                        if (inter > hib) {
                            s = -1.0f;
                        } else if (!(inter < lob)) {
                            if ((inter / uni) > 0.45f) s = -1.0f;  // exact IEEE div.rn
                        }
                    }
                }
                score[k] = s;
            }
            if (s > ls || (s == ls && gid < li)) { ls = s; li = gid; }
        }
    }

    if (rank == 0 && tid == 0) ond[img] = (float)ndet;

    // no CTA exits while peer DSMEM ops could be in flight
    asm volatile("barrier.cluster.arrive.aligned;" ::: "memory");
    asm volatile("barrier.cluster.wait.aligned;"   ::: "memory");
}

extern "C" void kernel_launch(void* const* d_in, const int* in_sizes, int n_in,
                              void* d_out, int out_size) {
    static bool attr_done = false;
    if (!attr_done) {
        cudaFuncSetAttribute(yolo_nms_kernel,
                             cudaFuncAttributeMaxDynamicSharedMemorySize, SMEM_BYTES);
        attr_done = true;
    }
    const float* in = (const float*)d_in[0];
    float* out = (float*)d_out;
    yolo_nms_kernel<<<BATCH * CLUSTER, NTHREADS, SMEM_BYTES>>>(in, out);
}

// round 8
// speedup vs baseline: 1.8822x; 1.0355x over previous
#include <cuda_runtime.h>
#include <float.h>
#include <cstdint>

#define NCH       36
#define NANCH     8400
#define NCLS      32
#define MAXDET    100
#define BATCH     64
#define NTHREADS  1024
#define CLUSTER   2
#define HALF_ANCH 4200            // anchors per CTA
#define KPT       5               // ceil(4200/1024)
#define CONF_T    0.25f

// dynamic smem per CTA: float4 box[4200] + area[4200] + cls[4200]
#define SMEM_BYTES ((4 + 1 + 1) * HALF_ANCH * 4)

struct alignas(16) Cand {
    unsigned u;      // order-preserving score key
    unsigned gidx;   // global anchor index
    float y1, x1, y2, x2;
    float area, cls;
};

__device__ __forceinline__ uint32_t smem_u32(const void* p) {
    uint32_t a;
    asm("{ .reg .u64 t; cvta.to.shared.u64 t, %1; cvt.u32.u64 %0, t; }" : "=r"(a) : "l"(p));
    return a;
}
__device__ __forceinline__ uint32_t mapa_u32(uint32_t a, uint32_t rank) {
    uint32_t o;
    asm("mapa.shared::cluster.u32 %0, %1, %2;" : "=r"(o) : "r"(a), "r"(rank));
    return o;
}
__device__ __forceinline__ void st_cluster(uint32_t a, unsigned v) {
    asm volatile("st.shared::cluster.u32 [%0], %1;" :: "r"(a), "r"(v) : "memory");
}
// monotone float -> u32 key (total order; bigger float => bigger key)
__device__ __forceinline__ unsigned fkey(float f) {
    unsigned b = __float_as_uint(f);
    return ((int)b >= 0) ? (b | 0x80000000u) : ~b;
}

__global__ __launch_bounds__(NTHREADS, 1) __cluster_dims__(CLUSTER, 1, 1)
void yolo_nms_kernel(const float* __restrict__ in, float* __restrict__ out) {
    extern __shared__ float smem[];
    float4* sbox  = (float4*)smem;             // [4200] (y1,x1,y2,x2)
    float*  sarea = smem + 4 * HALF_ANCH;      // [4200]
    float*  scls  = smem + 5 * HALF_ANCH;      // [4200]
    __shared__ Cand cand[2][64];               // parity-buffered, both CTAs' warp winners
    __shared__ unsigned long long cbar;        // mbarrier, 64 arrivals/phase

    const int tid  = threadIdx.x;
    const int lane = tid & 31;
    const int wid  = tid >> 5;
    unsigned rank;
    asm("mov.u32 %0, %%cluster_ctarank;" : "=r"(rank));
    const int img   = blockIdx.x >> 1;
    const int gbase = rank * HALF_ANCH;

    const float* base = in + (size_t)img * NCH * NANCH;

    float* ob  = out + (size_t)img * MAXDET * 4;
    float* oc  = out + (size_t)BATCH * MAXDET * 4 + (size_t)img * MAXDET;
    float* osc = out + (size_t)BATCH * MAXDET * 4 + (size_t)BATCH * MAXDET + (size_t)img * MAXDET;
    float* ond = out + (size_t)BATCH * MAXDET * 4 + (size_t)BATCH * MAXDET * 2;

    const uint32_t bar_a  = smem_u32(&cbar);
    const uint32_t peer   = rank ^ 1u;
    const uint32_t r_bar  = mapa_u32(bar_a, peer);
    const uint32_t r_cand = mapa_u32(smem_u32(&cand[0][0]), peer);

    if (tid == 0) {
        asm volatile("mbarrier.init.shared.b64 [%0], %1;" :: "r"(bar_a), "r"(64u) : "memory");
    }

    if (rank == 0) {
        for (int i = tid; i < MAXDET * 4; i += NTHREADS) ob[i] = 0.0f;
        if (tid < MAXDET) { oc[tid] = 0.0f; osc[tid] = 0.0f; }
    }

    // ---- Phase 1: preprocess this CTA's 4200 anchors ----
    float score[KPT];
    #pragma unroll
    for (int k = 0; k < KPT; k++) {
        int l = tid + k * NTHREADS;
        float s = -FLT_MAX;
        if (l < HALF_ANCH) {
            int ga = gbase + l;
            float xc = base[0 * NANCH + ga];
            float yc = base[1 * NANCH + ga];
            float w  = base[2 * NANCH + ga];
            float h  = base[3 * NANCH + ga];
            float best = -FLT_MAX;
            int cls = 0;
            #pragma unroll
            for (int c = 0; c < NCLS; c++) {
                float v = base[(4 + c) * NANCH + ga];
                if (v > best) { best = v; cls = c; }   // strict > == first-max
            }
            float y1 = fminf(fmaxf(yc - 0.5f * h, 0.0f), 1.0f);
            float x1 = fminf(fmaxf(xc - 0.5f * w, 0.0f), 1.0f);
            float y2 = fminf(fmaxf(yc + 0.5f * h, 0.0f), 1.0f);
            float x2 = fminf(fmaxf(xc + 0.5f * w, 0.0f), 1.0f);
            sbox[l]  = make_float4(y1, x1, y2, x2);
            sarea[l] = (y2 - y1) * (x2 - x1);
            scls[l]  = (float)cls;
            s = (best >= CONF_T) ? best : -1.0f;
        }
        score[k] = s;
    }
    __syncthreads();
    // mbarrier init + smem visible cluster-wide before any arrives
    asm volatile("barrier.cluster.arrive.aligned;" ::: "memory");
    asm volatile("barrier.cluster.wait.aligned;"   ::: "memory");

    // first local argmax (first-index tie-break; every thread owns >=1 real anchor)
    float ls = -FLT_MAX;
    int   li = 0x7FFFFFFF;
    #pragma unroll
    for (int k = 0; k < KPT; k++) {
        int gi = gbase + tid + k * NTHREADS;
        float s = score[k];
        if (s > ls || (s == ls && gi < li)) { ls = s; li = gi; }
    }

    int ndet = 0;
    for (int d = 0; d < MAXDET; d++) {
        const int p = d & 1;

        // ---- stage 1: warp argmax via redux (key desc, gidx asc) ----
        unsigned u  = fkey(ls);
        unsigned wu = __reduce_max_sync(0xFFFFFFFFu, u);
        unsigned ci = (u == wu) ? (unsigned)li : 0xFFFFFFFFu;
        unsigned wg = __reduce_min_sync(0xFFFFFFFFu, ci);

        // winner lane publishes full candidate record to BOTH CTAs, arrives on both bars
        if (u == wu && (unsigned)li == wg) {
            int l = li - gbase;
            float4 wb = sbox[l];
            int slot = (int)rank * 32 + wid;
            Cand c;
            c.u = wu; c.gidx = wg;
            c.y1 = wb.x; c.x1 = wb.y; c.y2 = wb.z; c.x2 = wb.w;
            c.area = sarea[l]; c.cls = scls[l];
            cand[p][slot] = c;                       // local copy
            uint32_t rm = r_cand + (uint32_t)(p * 64 + slot) * sizeof(Cand);
            st_cluster(rm + 0,  wu);
            st_cluster(rm + 4,  wg);
            st_cluster(rm + 8,  __float_as_uint(wb.x));
            st_cluster(rm + 12, __float_as_uint(wb.y));
            st_cluster(rm + 16, __float_as_uint(wb.z));
            st_cluster(rm + 20, __float_as_uint(wb.w));
            st_cluster(rm + 24, __float_as_uint(c.area));
            st_cluster(rm + 28, __float_as_uint(c.cls));
            asm volatile("mbarrier.arrive.shared.b64 _, [%0];" :: "r"(bar_a) : "memory");
            asm volatile("mbarrier.arrive.release.cluster.shared::cluster.b64 _, [%0];"
                         :: "r"(r_bar) : "memory");
        }

        // ---- wait: 64 arrivals (32 local + 32 remote), acquire at cluster scope ----
        {
            unsigned done;
            asm volatile(
                "{\n\t.reg .pred q;\n\t"
                "mbarrier.try_wait.parity.acquire.cluster.shared::cta.b64 q, [%1], %2, 0x989680;\n\t"
                "selp.b32 %0, 1, 0, q;\n\t}"
                : "=r"(done) : "r"(bar_a), "r"((unsigned)p) : "memory");
            if (!done) {
                asm volatile(
                    "{\n\t.reg .pred Q1;\n\t"
                    "WL_%=:\n\t"
                    "mbarrier.try_wait.parity.acquire.cluster.shared::cta.b64 Q1, [%0], %1, 0x989680;\n\t"
                    "@Q1 bra.uni WD_%=;\n\t"
                    "bra.uni WL_%=;\n\t"
                    "WD_%=:\n\t}"
                    :: "r"(bar_a), "r"((unsigned)p) : "memory");
            }
        }

        // ---- stage 2: reduce 64 candidates (2 per lane), every warp redundantly ----
        uint2 a0 = *(const uint2*)&cand[p][lane];
        uint2 a1 = *(const uint2*)&cand[p][lane + 32];
        unsigned mu, mg; int mslot;
        bool pick1 = (a1.x > a0.x) || (a1.x == a0.x && a1.y < a0.y);
        mu = pick1 ? a1.x : a0.x;
        mg = pick1 ? a1.y : a0.y;
        mslot = pick1 ? (lane + 32) : lane;

        unsigned wu2 = __reduce_max_sync(0xFFFFFFFFu, mu);
        unsigned cg2 = (mu == wu2) ? mg : 0xFFFFFFFFu;
        unsigned wg2 = __reduce_min_sync(0xFFFFFFFFu, cg2);

        if (wu2 <= 0x80000000u) break;   // winner score <= 0.0 -> done (uniform)
        ndet++;

        unsigned msk = __ballot_sync(0xFFFFFFFFu, mu == wu2 && mg == wg2);
        int slot = __shfl_sync(0xFFFFFFFFu, mslot, __ffs(msk) - 1);

        const Cand* w = &cand[p][slot];     // broadcast LDS (same address all lanes)
        float4 bb = make_float4(w->y1, w->x1, w->y2, w->x2);
        float  ba = w->area;
        int    gi = (int)wg2;

        if (rank == 0 && tid == 0) {
            float sraw = (wu2 & 0x80000000u) ? __uint_as_float(wu2 ^ 0x80000000u)
                                             : __uint_as_float(~wu2);
            ob[d * 4 + 0] = bb.x; ob[d * 4 + 1] = bb.y;
            ob[d * 4 + 2] = bb.z; ob[d * 4 + 3] = bb.w;
            oc[d]  = w->cls;
            osc[d] = sraw;
        }

        // ---- fused suppress + next local argmax ----
        ls = -FLT_MAX;
        li = 0x7FFFFFFF;
        #pragma unroll
        for (int k = 0; k < KPT; k++) {
            int l   = tid + k * NTHREADS;
            int gid = gbase + l;
            float s = score[k];
            if (s > 0.0f) {
                if (gid == gi) {
                    s = -1.0f;
                } else {
                    float4 b  = sbox[l];
                    float  ab = sarea[l];
                    float yy1 = fmaxf(bb.x, b.x);
                    float xx1 = fmaxf(bb.y, b.y);
                    float yy2 = fminf(bb.z, b.z);
                    float xx2 = fminf(bb.w, b.w);
                    float inter = fmaxf(yy2 - yy1, 0.0f) * fmaxf(xx2 - xx1, 0.0f);
                    float uni = ba + ab - inter;   // area_a + area_b - inter (ref order)
                    if (uni > 0.0f) {
                        float hib = 0.45000051f * uni;   // +1.1e-6 rel guard
                        float lob = 0.44999949f * uni;   // -1.1e-6 rel guard
                        if (inter > hib) {
                            s = -1.0f;
                        } else if (!(inter < lob)) {
                            if ((inter / uni) > 0.45f) s = -1.0f;  // exact IEEE div.rn
                        }
                    }
                }
                score[k] = s;
            }
            if (s > ls || (s == ls && gid < li)) { ls = s; li = gid; }
        }
    }

    if (rank == 0 && tid == 0) ond[img] = (float)ndet;

    // no CTA exits while peer DSMEM ops could be in flight
    asm volatile("barrier.cluster.arrive.aligned;" ::: "memory");
    asm volatile("barrier.cluster.wait.aligned;"   ::: "memory");
}

extern "C" void kernel_launch(void* const* d_in, const int* in_sizes, int n_in,
                              void* d_out, int out_size) {
    static bool attr_done = false;
    if (!attr_done) {
        cudaFuncSetAttribute(yolo_nms_kernel,
                             cudaFuncAttributeMaxDynamicSharedMemorySize, SMEM_BYTES);
        attr_done = true;
    }
    const float* in = (const float*)d_in[0];
    float* out = (float*)d_out;
    yolo_nms_kernel<<<BATCH * CLUSTER, NTHREADS, SMEM_BYTES>>>(in, out);
}

// round 9
// speedup vs baseline: 2.2112x; 1.1748x over previous
#include <cuda_runtime.h>
#include <float.h>
#include <cstdint>

#define NCH       36
#define NANCH     8400
#define NCLS      32
#define MAXDET    100
#define BATCH     64
#define NTHREADS  1024
#define CLUSTER   2
#define HALF_ANCH 4200            // anchors per CTA
#define KPT       5               // ceil(4200/1024)
#define CONF_T    0.25f
// iou > 0.45  <=>  inter > (0.45/1.45)*(A+B)   [valid: inter>0 => union>0]
#define C_HI      0.31034523f     // c*(1+~1.3e-6)
#define C_LO      0.31034442f     // c*(1-~1.3e-6)

// dynamic smem per CTA: float4 box[4200] + area[4200] + cls[4200]
#define SMEM_BYTES ((4 + 1 + 1) * HALF_ANCH * 4)

struct alignas(16) Rec {            // winner record (broadcast-read only)
    float y1, x1, y2, x2;
    float area, cls;
    float pad0, pad1;
};

__device__ __forceinline__ uint32_t smem_u32(const void* p) {
    uint32_t a;
    asm("{ .reg .u64 t; cvta.to.shared.u64 t, %1; cvt.u32.u64 %0, t; }" : "=r"(a) : "l"(p));
    return a;
}
__device__ __forceinline__ uint32_t mapa_u32(uint32_t a, uint32_t rank) {
    uint32_t o;
    asm("mapa.shared::cluster.u32 %0, %1, %2;" : "=r"(o) : "r"(a), "r"(rank));
    return o;
}
__device__ __forceinline__ void st_cluster(uint32_t a, unsigned v) {
    asm volatile("st.shared::cluster.u32 [%0], %1;" :: "r"(a), "r"(v) : "memory");
}
// monotone float -> u32 key (bigger float => bigger key); fkey(0.0f)=0x80000000
__device__ __forceinline__ unsigned fkey(float f) {
    unsigned b = __float_as_uint(f);
    return ((int)b >= 0) ? (b | 0x80000000u) : ~b;
}

__global__ __launch_bounds__(NTHREADS, 1) __cluster_dims__(CLUSTER, 1, 1)
void yolo_nms_kernel(const float* __restrict__ in, float* __restrict__ out) {
    extern __shared__ float smem[];
    float4* sbox  = (float4*)smem;             // [4200] (y1,x1,y2,x2)
    float*  sarea = smem + 4 * HALF_ANCH;      // [4200]
    float*  scls  = smem + 5 * HALF_ANCH;      // [4200]
    __shared__ uint2 ckey[2][64];              // (key, gidx), conflict-free 8B stride
    __shared__ Rec   crec[2][64];              // winner records
    __shared__ unsigned long long cbar;        // mbarrier, 64 arrivals/phase

    const int tid  = threadIdx.x;
    const int lane = tid & 31;
    const int wid  = tid >> 5;
    unsigned rank;
    asm("mov.u32 %0, %%cluster_ctarank;" : "=r"(rank));
    const int img   = blockIdx.x >> 1;
    const int gbase = rank * HALF_ANCH;

    const float* base = in + (size_t)img * NCH * NANCH;

    float* ob  = out + (size_t)img * MAXDET * 4;
    float* oc  = out + (size_t)BATCH * MAXDET * 4 + (size_t)img * MAXDET;
    float* osc = out + (size_t)BATCH * MAXDET * 4 + (size_t)BATCH * MAXDET + (size_t)img * MAXDET;
    float* ond = out + (size_t)BATCH * MAXDET * 4 + (size_t)BATCH * MAXDET * 2;

    const uint32_t bar_a  = smem_u32(&cbar);
    const uint32_t peer   = rank ^ 1u;
    const uint32_t r_bar  = mapa_u32(bar_a, peer);
    const uint32_t r_ckey = mapa_u32(smem_u32(&ckey[0][0]), peer);
    const uint32_t r_crec = mapa_u32(smem_u32(&crec[0][0]), peer);

    if (tid == 0) {
        asm volatile("mbarrier.init.shared.b64 [%0], %1;" :: "r"(bar_a), "r"(64u) : "memory");
    }

    if (rank == 0) {
        for (int i = tid; i < MAXDET * 4; i += NTHREADS) ob[i] = 0.0f;
        if (tid < MAXDET) { oc[tid] = 0.0f; osc[tid] = 0.0f; }
    }

    // ---- Phase 1: preprocess this CTA's 4200 anchors ----
    unsigned ukey[KPT];
    #pragma unroll
    for (int k = 0; k < KPT; k++) {
        int l = tid + k * NTHREADS;
        unsigned ku = 0u;
        if (l < HALF_ANCH) {
            int ga = gbase + l;
            float xc = base[0 * NANCH + ga];
            float yc = base[1 * NANCH + ga];
            float w  = base[2 * NANCH + ga];
            float h  = base[3 * NANCH + ga];
            float best = -FLT_MAX;
            int cls = 0;
            #pragma unroll
            for (int c = 0; c < NCLS; c++) {
                float v = base[(4 + c) * NANCH + ga];
                if (v > best) { best = v; cls = c; }   // strict > == first-max
            }
            float y1 = fminf(fmaxf(yc - 0.5f * h, 0.0f), 1.0f);
            float x1 = fminf(fmaxf(xc - 0.5f * w, 0.0f), 1.0f);
            float y2 = fminf(fmaxf(yc + 0.5f * h, 0.0f), 1.0f);
            float x2 = fminf(fmaxf(xc + 0.5f * w, 0.0f), 1.0f);
            sbox[l]  = make_float4(y1, x1, y2, x2);
            sarea[l] = (y2 - y1) * (x2 - x1);
            scls[l]  = (float)cls;
            // masked (<CONF) anchors are dead from the start: they are -1 in the
            // reference, can never be selected, and suppression leaves them -1.
            if (best >= CONF_T) ku = fkey(best);   // > 0x80000000 for best>0
        }
        ukey[k] = ku;
    }
    __syncthreads();
    asm volatile("barrier.cluster.arrive.aligned;" ::: "memory");
    asm volatile("barrier.cluster.wait.aligned;"   ::: "memory");

    // first local argmax: descending k + '>=' => lowest gid on ties
    unsigned lk = 0u;
    int      li = gbase + tid;
    #pragma unroll
    for (int k = KPT - 1; k >= 0; k--) {
        int gid = gbase + tid + k * NTHREADS;
        unsigned ku = ukey[k];
        if (ku >= lk) { lk = ku; li = gid; }
    }

    int ndet = 0;
    for (int d = 0; d < MAXDET; d++) {
        const int p = d & 1;

        // ---- stage 1: warp argmax via redux (key desc, gidx asc) ----
        unsigned wu = __reduce_max_sync(0xFFFFFFFFu, lk);
        unsigned ci = (lk == wu) ? (unsigned)li : 0xFFFFFFFFu;
        unsigned wg = __reduce_min_sync(0xFFFFFFFFu, ci);

        // winner lane publishes to BOTH CTAs, arrives on both barriers
        if (lk == wu && (unsigned)li == wg) {
            int l = (int)wg - gbase;
            float4 wb = sbox[l];
            float  wa = sarea[l];
            float  wc = scls[l];
            int slot = (int)rank * 32 + wid;
            ckey[p][slot] = make_uint2(wu, wg);
            Rec rc; rc.y1 = wb.x; rc.x1 = wb.y; rc.y2 = wb.z; rc.x2 = wb.w;
            rc.area = wa; rc.cls = wc; rc.pad0 = 0.f; rc.pad1 = 0.f;
            crec[p][slot] = rc;
            uint32_t rk = r_ckey + (uint32_t)(p * 64 + slot) * 8u;
            st_cluster(rk + 0, wu);
            st_cluster(rk + 4, wg);
            uint32_t rr = r_crec + (uint32_t)(p * 64 + slot) * sizeof(Rec);
            st_cluster(rr + 0,  __float_as_uint(wb.x));
            st_cluster(rr + 4,  __float_as_uint(wb.y));
            st_cluster(rr + 8,  __float_as_uint(wb.z));
            st_cluster(rr + 12, __float_as_uint(wb.w));
            st_cluster(rr + 16, __float_as_uint(wa));
            st_cluster(rr + 20, __float_as_uint(wc));
            asm volatile("mbarrier.arrive.shared.b64 _, [%0];" :: "r"(bar_a) : "memory");
            asm volatile("mbarrier.arrive.release.cluster.shared::cluster.b64 _, [%0];"
                         :: "r"(r_bar) : "memory");
        }

        // ---- wait: 64 arrivals (32 local + 32 remote) ----
        {
            unsigned done;
            asm volatile(
                "{\n\t.reg .pred q;\n\t"
                "mbarrier.try_wait.parity.acquire.cluster.shared::cta.b64 q, [%1], %2, 0x989680;\n\t"
                "selp.b32 %0, 1, 0, q;\n\t}"
                : "=r"(done) : "r"(bar_a), "r"((unsigned)p) : "memory");
            if (!done) {
                asm volatile(
                    "{\n\t.reg .pred Q1;\n\t"
                    "WL_%=:\n\t"
                    "mbarrier.try_wait.parity.acquire.cluster.shared::cta.b64 Q1, [%0], %1, 0x989680;\n\t"
                    "@Q1 bra.uni WD_%=;\n\t"
                    "bra.uni WL_%=;\n\t"
                    "WD_%=:\n\t}"
                    :: "r"(bar_a), "r"((unsigned)p) : "memory");
            }
        }

        // ---- stage 2: reduce 64 candidates (2/lane), every warp redundantly ----
        uint2 a0 = ckey[p][lane];
        uint2 a1 = ckey[p][lane + 32];
        bool pick1 = (a1.x > a0.x) || (a1.x == a0.x && a1.y < a0.y);
        unsigned mu = pick1 ? a1.x : a0.x;
        unsigned mg = pick1 ? a1.y : a0.y;
        int   mslot = pick1 ? (lane + 32) : lane;

        unsigned wu2 = __reduce_max_sync(0xFFFFFFFFu, mu);
        unsigned cg2 = (mu == wu2) ? mg : 0xFFFFFFFFu;
        unsigned wg2 = __reduce_min_sync(0xFFFFFFFFu, cg2);

        if (wu2 <= 0x80000000u) break;   // winner score <= 0 -> done (uniform)
        ndet++;

        unsigned msk = __ballot_sync(0xFFFFFFFFu, mu == wu2 && mg == wg2);
        int slot = __shfl_sync(0xFFFFFFFFu, mslot, __ffs(msk) - 1);

        const Rec* w = &crec[p][slot];     // broadcast LDS
        float4 bb = make_float4(w->y1, w->x1, w->y2, w->x2);
        float  ba = w->area;
        int    gi = (int)wg2;

        if (rank == 0 && tid == 0) {
            float sraw = (wu2 & 0x80000000u) ? __uint_as_float(wu2 & 0x7FFFFFFFu)
                                             : __uint_as_float(~wu2);
            ob[d * 4 + 0] = bb.x; ob[d * 4 + 1] = bb.y;
            ob[d * 4 + 2] = bb.z; ob[d * 4 + 3] = bb.w;
            oc[d]  = w->cls;
            osc[d] = sraw;
        }

        // ---- fused suppress + next local argmax (div-free, union-free IoU) ----
        lk = 0u;
        li = gbase + tid;
        #pragma unroll
        for (int k = KPT - 1; k >= 0; k--) {
            int l   = tid + k * NTHREADS;
            int gid = gbase + l;
            unsigned ku = ukey[k];
            if (ku != 0u) {
                float4 b  = sbox[l];
                float  ab = sarea[l];
                float yy1 = fmaxf(bb.x, b.x);
                float xx1 = fmaxf(bb.y, b.y);
                float yy2 = fminf(bb.z, b.z);
                float xx2 = fminf(bb.w, b.w);
                float inter = fmaxf(yy2 - yy1, 0.0f) * fmaxf(xx2 - xx1, 0.0f);
                float S = ba + ab;
                bool kill = (gid == gi) || (inter > C_HI * S);
                if (!kill && !(inter < C_LO * S)) {
                    // ambiguous band: replicate reference ops exactly
                    float uni = ba + ab - inter;
                    if (uni > 0.0f) kill = (inter / uni) > 0.45f;
                }
                if (kill) { ku = 0u; ukey[k] = 0u; }
            }
            if (ku >= lk) { lk = ku; li = gid; }
        }
    }

    if (rank == 0 && tid == 0) ond[img] = (float)ndet;

    asm volatile("barrier.cluster.arrive.aligned;" ::: "memory");
    asm volatile("barrier.cluster.wait.aligned;"   ::: "memory");
}

extern "C" void kernel_launch(void* const* d_in, const int* in_sizes, int n_in,
                              void* d_out, int out_size) {
    static bool attr_done = false;
    if (!attr_done) {
        cudaFuncSetAttribute(yolo_nms_kernel,
                             cudaFuncAttributeMaxDynamicSharedMemorySize, SMEM_BYTES);
        attr_done = true;
    }
    const float* in = (const float*)d_in[0];
    float* out = (float*)d_out;
    yolo_nms_kernel<<<BATCH * CLUSTER, NTHREADS, SMEM_BYTES>>>(in, out);
}

// round 10
// speedup vs baseline: 2.2602x; 1.0222x over previous
#include <cuda_runtime.h>
#include <float.h>
#include <cstdint>

#define NCH       36
#define NANCH     8400
#define NCLS      32
#define MAXDET    100
#define BATCH     64
#define NTHREADS  1024
#define CLUSTER   2
#define HALF_ANCH 4200            // anchors per CTA
#define KPT       5               // ceil(4200/1024)
#define CONF_T    0.25f
// iou > 0.45  <=>  inter > (0.45/1.45)*(A+B)   [valid: inter>0 => union>0]
#define C_HI      0.31034523f     // c*(1+~1.3e-6)
#define C_LO      0.31034442f     // c*(1-~1.3e-6)

// dynamic smem per CTA: float4 box[4200] + area[4200] + cls[4200]
#define SMEM_BYTES ((4 + 1 + 1) * HALF_ANCH * 4)

struct alignas(16) Rec {            // winner record (broadcast-read only)
    float y1, x1, y2, x2;
    float area, cls;
    float pad0, pad1;
};

__device__ __forceinline__ uint32_t smem_u32(const void* p) {
    uint32_t a;
    asm("{ .reg .u64 t; cvta.to.shared.u64 t, %1; cvt.u32.u64 %0, t; }" : "=r"(a) : "l"(p));
    return a;
}
__device__ __forceinline__ uint32_t mapa_u32(uint32_t a, uint32_t rank) {
    uint32_t o;
    asm("mapa.shared::cluster.u32 %0, %1, %2;" : "=r"(o) : "r"(a), "r"(rank));
    return o;
}
__device__ __forceinline__ void st_cluster(uint32_t a, unsigned v) {
    asm volatile("st.shared::cluster.u32 [%0], %1;" :: "r"(a), "r"(v) : "memory");
}
// monotone float -> u32 key (bigger float => bigger key); fkey(0.0f)=0x80000000
__device__ __forceinline__ unsigned fkey(float f) {
    unsigned b = __float_as_uint(f);
    return ((int)b >= 0) ? (b | 0x80000000u) : ~b;
}

__global__ __launch_bounds__(NTHREADS, 1) __cluster_dims__(CLUSTER, 1, 1)
void yolo_nms_kernel(const float* __restrict__ in, float* __restrict__ out) {
    extern __shared__ float smem[];
    float4* sbox  = (float4*)smem;             // [4200] (y1,x1,y2,x2)
    float*  sarea = smem + 4 * HALF_ANCH;      // [4200]
    float*  scls  = smem + 5 * HALF_ANCH;      // [4200]
    __shared__ uint2 ckey[2][64];              // (key, gidx), parity-buffered
    __shared__ Rec   crec[2][64];              // winner records
    __shared__ unsigned long long cbar;        // mbarrier, 64 arrivals/phase

    const int tid  = threadIdx.x;
    const int lane = tid & 31;
    const int wid  = tid >> 5;
    unsigned rank;
    asm("mov.u32 %0, %%cluster_ctarank;" : "=r"(rank));
    const int img   = blockIdx.x >> 1;
    const int gbase = rank * HALF_ANCH;

    const float* base = in + (size_t)img * NCH * NANCH;

    float* ob  = out + (size_t)img * MAXDET * 4;
    float* oc  = out + (size_t)BATCH * MAXDET * 4 + (size_t)img * MAXDET;
    float* osc = out + (size_t)BATCH * MAXDET * 4 + (size_t)BATCH * MAXDET + (size_t)img * MAXDET;
    float* ond = out + (size_t)BATCH * MAXDET * 4 + (size_t)BATCH * MAXDET * 2;

    const uint32_t bar_a  = smem_u32(&cbar);
    const uint32_t peer   = rank ^ 1u;
    const uint32_t r_bar  = mapa_u32(bar_a, peer);
    const uint32_t r_ckey = mapa_u32(smem_u32(&ckey[0][0]), peer);
    const uint32_t r_crec = mapa_u32(smem_u32(&crec[0][0]), peer);

    if (tid == 0) {
        asm volatile("mbarrier.init.shared.b64 [%0], %1;" :: "r"(bar_a), "r"(64u) : "memory");
    }

    if (rank == 0) {
        for (int i = tid; i < MAXDET * 4; i += NTHREADS) ob[i] = 0.0f;
        if (tid < MAXDET) { oc[tid] = 0.0f; osc[tid] = 0.0f; }
    }

    // ---- Phase 1: preprocess this CTA's 4200 anchors ----
    unsigned ukey[KPT];
    #pragma unroll
    for (int k = 0; k < KPT; k++) {
        int l = tid + k * NTHREADS;
        unsigned ku = 0u;
        if (l < HALF_ANCH) {
            int ga = gbase + l;
            float xc = base[0 * NANCH + ga];
            float yc = base[1 * NANCH + ga];
            float w  = base[2 * NANCH + ga];
            float h  = base[3 * NANCH + ga];
            float best = -FLT_MAX;
            int cls = 0;
            #pragma unroll
            for (int c = 0; c < NCLS; c++) {
                float v = base[(4 + c) * NANCH + ga];
                if (v > best) { best = v; cls = c; }   // strict > == first-max
            }
            float y1 = fminf(fmaxf(yc - 0.5f * h, 0.0f), 1.0f);
            float x1 = fminf(fmaxf(xc - 0.5f * w, 0.0f), 1.0f);
            float y2 = fminf(fmaxf(yc + 0.5f * h, 0.0f), 1.0f);
            float x2 = fminf(fmaxf(xc + 0.5f * w, 0.0f), 1.0f);
            sbox[l]  = make_float4(y1, x1, y2, x2);
            sarea[l] = (y2 - y1) * (x2 - x1);
            scls[l]  = (float)cls;
            // masked (<CONF) anchors are dead from the start (ref: -1 forever)
            if (best >= CONF_T) ku = fkey(best);   // > 0x80000000 for best>0
        }
        ukey[k] = ku;
    }
    __syncthreads();
    asm volatile("barrier.cluster.arrive.aligned;" ::: "memory");
    asm volatile("barrier.cluster.wait.aligned;"   ::: "memory");

    // first local argmax: descending k + '>=' => lowest gid on ties
    unsigned lk = 0u;
    int      li = gbase + tid;
    #pragma unroll
    for (int k = KPT - 1; k >= 0; k--) {
        int gid = gbase + tid + k * NTHREADS;
        unsigned ku = ukey[k];
        if (ku >= lk) { lk = ku; li = gid; }
    }

    int ndet = 0;
    for (int d = 0; d < MAXDET; d++) {
        const int p = d & 1;

        // ---- stage 1: warp argmax via redux (key desc, gidx asc) ----
        unsigned wu = __reduce_max_sync(0xFFFFFFFFu, lk);
        unsigned ci = (lk == wu) ? (unsigned)li : 0xFFFFFFFFu;
        unsigned wg = __reduce_min_sync(0xFFFFFFFFu, ci);

        // winner lane publishes to BOTH CTAs, arrives on both barriers
        if (lk == wu && (unsigned)li == wg) {
            int l = (int)wg - gbase;
            float4 wb = sbox[l];
            float  wa = sarea[l];
            float  wc = scls[l];
            int slot = (int)rank * 32 + wid;
            ckey[p][slot] = make_uint2(wu, wg);
            Rec rc; rc.y1 = wb.x; rc.x1 = wb.y; rc.y2 = wb.z; rc.x2 = wb.w;
            rc.area = wa; rc.cls = wc; rc.pad0 = 0.f; rc.pad1 = 0.f;
            crec[p][slot] = rc;
            uint32_t rk = r_ckey + (uint32_t)(p * 64 + slot) * 8u;
            st_cluster(rk + 0, wu);
            st_cluster(rk + 4, wg);
            uint32_t rr = r_crec + (uint32_t)(p * 64 + slot) * sizeof(Rec);
            st_cluster(rr + 0,  __float_as_uint(wb.x));
            st_cluster(rr + 4,  __float_as_uint(wb.y));
            st_cluster(rr + 8,  __float_as_uint(wb.z));
            st_cluster(rr + 12, __float_as_uint(wb.w));
            st_cluster(rr + 16, __float_as_uint(wa));
            st_cluster(rr + 20, __float_as_uint(wc));
            asm volatile("mbarrier.arrive.shared.b64 _, [%0];" :: "r"(bar_a) : "memory");
            asm volatile("mbarrier.arrive.release.cluster.shared::cluster.b64 _, [%0];"
                         :: "r"(r_bar) : "memory");
        }

        // ---- wait: 64 arrivals (32 local + 32 remote) ----
        {
            unsigned done;
            asm volatile(
                "{\n\t.reg .pred q;\n\t"
                "mbarrier.try_wait.parity.acquire.cluster.shared::cta.b64 q, [%1], %2, 0x989680;\n\t"
                "selp.b32 %0, 1, 0, q;\n\t}"
                : "=r"(done) : "r"(bar_a), "r"((unsigned)p) : "memory");
            if (!done) {
                asm volatile(
                    "{\n\t.reg .pred Q1;\n\t"
                    "WL_%=:\n\t"
                    "mbarrier.try_wait.parity.acquire.cluster.shared::cta.b64 Q1, [%0], %1, 0x989680;\n\t"
                    "@Q1 bra.uni WD_%=;\n\t"
                    "bra.uni WL_%=;\n\t"
                    "WD_%=:\n\t}"
                    :: "r"(bar_a), "r"((unsigned)p) : "memory");
            }
        }

        // ---- stage 2: reduce 64 candidates (2/lane), every warp redundantly ----
        uint2 a0 = ckey[p][lane];
        uint2 a1 = ckey[p][lane + 32];
        bool pick1 = (a1.x > a0.x) || (a1.x == a0.x && a1.y < a0.y);
        unsigned mu = pick1 ? a1.x : a0.x;
        unsigned mg = pick1 ? a1.y : a0.y;
        int   mslot = pick1 ? (lane + 32) : lane;

        unsigned wu2 = __reduce_max_sync(0xFFFFFFFFu, mu);
        unsigned cg2 = (mu == wu2) ? mg : 0xFFFFFFFFu;
        unsigned wg2 = __reduce_min_sync(0xFFFFFFFFu, cg2);

        if (wu2 <= 0x80000000u) break;   // winner score <= 0 -> done (uniform)
        ndet++;

        unsigned msk = __ballot_sync(0xFFFFFFFFu, mu == wu2 && mg == wg2);
        int slot = __shfl_sync(0xFFFFFFFFu, mslot, __ffs(msk) - 1);

        const Rec* w = &crec[p][slot];     // broadcast LDS
        float4 bb = make_float4(w->y1, w->x1, w->y2, w->x2);
        float  ba = w->area;
        int    gi = (int)wg2;

        if (rank == 0 && tid == 0) {
            float sraw = (wu2 & 0x80000000u) ? __uint_as_float(wu2 & 0x7FFFFFFFu)
                                             : __uint_as_float(~wu2);
            ob[d * 4 + 0] = bb.x; ob[d * 4 + 1] = bb.y;
            ob[d * 4 + 2] = bb.z; ob[d * 4 + 3] = bb.w;
            oc[d]  = w->cls;
            osc[d] = sraw;
        }

        // winner kill by owning thread (NTHREADS=1024 is pow2: tid = lloc & 1023)
        // replicates the reference's unconditional at[idx].set(-1), incl. the
        // zero-area corner case where the IoU path would not fire.
        {
            int lloc = gi - gbase;
            if ((unsigned)lloc < HALF_ANCH && (lloc & (NTHREADS - 1)) == tid)
                ukey[lloc >> 10] = 0u;
        }

        // ---- warp dead-skip: lk==0 <=> this thread owns no live anchor.
        // Kills are spatially (= index) contiguous, so whole warps go dead.
        if (__ballot_sync(0xFFFFFFFFu, lk != 0u) == 0u) {
            lk = 0u;
            li = gbase + tid;
            continue;    // loop trip count stays uniform: break decision is wu2
        }

        // ---- fused suppress + next local argmax (div-free, union-free IoU) ----
        lk = 0u;
        li = gbase + tid;
        #pragma unroll
        for (int k = KPT - 1; k >= 0; k--) {
            int l   = tid + k * NTHREADS;
            int gid = gbase + l;
            unsigned ku = ukey[k];
            if (ku != 0u) {
                float4 b  = sbox[l];
                float  ab = sarea[l];
                float yy1 = fmaxf(bb.x, b.x);
                float xx1 = fmaxf(bb.y, b.y);
                float yy2 = fminf(bb.z, b.z);
                float xx2 = fminf(bb.w, b.w);
                float inter = fmaxf(yy2 - yy1, 0.0f) * fmaxf(xx2 - xx1, 0.0f);
                float S = ba + ab;
                bool kill = inter > C_HI * S;
                if (!kill && !(inter < C_LO * S)) {
                    // ambiguous band: replicate reference ops exactly
                    float uni = ba + ab - inter;
                    if (uni > 0.0f) kill = (inter / uni) > 0.45f;
                }
                if (kill) { ku = 0u; ukey[k] = 0u; }
            }
            if (ku >= lk) { lk = ku; li = gid; }
        }
    }

    if (rank == 0 && tid == 0) ond[img] = (float)ndet;

    asm volatile("barrier.cluster.arrive.aligned;" ::: "memory");
    asm volatile("barrier.cluster.wait.aligned;"   ::: "memory");
}

extern "C" void kernel_launch(void* const* d_in, const int* in_sizes, int n_in,
                              void* d_out, int out_size) {
    static bool attr_done = false;
    if (!attr_done) {
        cudaFuncSetAttribute(yolo_nms_kernel,
                             cudaFuncAttributeMaxDynamicSharedMemorySize, SMEM_BYTES);
        attr_done = true;
    }
    const float* in = (const float*)d_in[0];
    float* out = (float*)d_out;
    yolo_nms_kernel<<<BATCH * CLUSTER, NTHREADS, SMEM_BYTES>>>(in, out);
}